// round 10
// baseline (speedup 1.0000x reference)
#include <cuda_runtime.h>
#include <cuda_bf16.h>

// ============================================================================
// TransitionDown: FPS (M=8192 of N=32768) + kNN(16) + Linear+BN+ReLU + max-pool
// Output layout (float32): [out 8192x256][sub_pos 8192x3][sub_batch 8192]
// All arithmetic exact f32 (reference matmuls are exact-f32 scale).
// ============================================================================

#define NPTS   32768
#define CIN    128
#define COUT   256
#define KNN_K  16
#define MCL    8192

#define FPS_CTAS    8
#define FPS_THREADS 512
#define PPT         8   // points per thread: 8*512*8 = 32768

// ---------------- device scratch (static; no allocation allowed) ------------
__device__ float4 g_pos4[NPTS];            // {x,y,z, |p|^2} exact f32
__device__ int    g_idx[MCL];              // FPS-selected indices
__device__ int    g_nbr[MCL * KNN_K];      // kNN indices
__device__ float  g_h[NPTS * COUT];        // linear output (pre-BN)
__device__ float  g_psum[256 * COUT];
__device__ float  g_psumsq[256 * COUT];
__device__ float  g_scale[COUT];
__device__ float  g_shift[COUT];

// ---------------- small helpers ---------------------------------------------
__device__ __forceinline__ float finf() { return __int_as_float(0x7f800000); }
__device__ __forceinline__ float fninf() { return __int_as_float(0xff800000); }

__device__ __forceinline__ unsigned long long pk2(float a, float b) {
    unsigned long long r;
    asm("mov.b64 %0, {%1, %2};" : "=l"(r) : "f"(a), "f"(b));
    return r;
}
__device__ __forceinline__ void upk2(unsigned long long v, float& a, float& b) {
    asm("mov.b64 {%0, %1}, %2;" : "=f"(a), "=f"(b) : "l"(v));
}
__device__ __forceinline__ unsigned long long add2(unsigned long long a, unsigned long long b) {
    unsigned long long r;
    asm("add.rn.f32x2 %0, %1, %2;" : "=l"(r) : "l"(a), "l"(b));
    return r;
}
__device__ __forceinline__ unsigned long long mul2(unsigned long long a, unsigned long long b) {
    unsigned long long r;
    asm("mul.rn.f32x2 %0, %1, %2;" : "=l"(r) : "l"(a), "l"(b));
    return r;
}
// store u64 into the same smem offset of a peer CTA in the cluster
__device__ __forceinline__ void st_cluster_u64(unsigned laddr, unsigned rank,
                                               unsigned long long v) {
    asm volatile(
        "{\n\t"
        ".reg .b32 ra;\n\t"
        "mapa.shared::cluster.u32 ra, %0, %1;\n\t"
        "st.shared::cluster.u64 [ra], %2;\n\t"
        "}"
        :: "r"(laddr), "r"(rank), "l"(v) : "memory");
}
__device__ __forceinline__ unsigned cluster_rank() {
    unsigned r;
    asm("mov.u32 %0, %%cluster_ctarank;" : "=r"(r));
    return r;
}

// ============================================================================
// 0) prep: pos4 table {x,y,z, |p|^2} exact f32
// ============================================================================
__global__ void prep_kernel(const float* __restrict__ pos) {
    int i = blockIdx.x * blockDim.x + threadIdx.x;
    if (i >= NPTS) return;
    float x = pos[3 * i + 0];
    float y = pos[3 * i + 1];
    float z = pos[3 * i + 2];
    float n = __fadd_rn(__fadd_rn(__fmul_rn(x, x), __fmul_rn(y, y)), __fmul_rn(z, z));
    g_pos4[i] = make_float4(x, y, z, n);
}

// ============================================================================
// 1) FPS: 8-CTA cluster, points register-resident, 1 cluster.sync per round.
//    Exact f32, same op order as reference: ((dx^2+dy^2)+dz^2).
//    Argmax key = (dist_bits<<32) | (0xFFFFFFFF - idx) -> first-index ties.
// ============================================================================
__global__ void __cluster_dims__(FPS_CTAS, 1, 1) __launch_bounds__(FPS_THREADS, 1)
fps_kernel(const float* __restrict__ pos) {
    __shared__ float4 s_center;
    __shared__ unsigned long long s_wslots[FPS_THREADS / 32];
    __shared__ unsigned long long s_cross[2][FPS_CTAS];

    const int tid = threadIdx.x;
    const unsigned rank = cluster_rank();
    const int p0 = (int)(rank * FPS_THREADS + tid) * PPT;

    unsigned long long X[PPT / 2], Y[PPT / 2], Z[PPT / 2];
    float md[PPT];
#pragma unroll
    for (int pr = 0; pr < PPT / 2; ++pr) {
        int a = p0 + 2 * pr, b = a + 1;
        X[pr] = pk2(pos[3 * a + 0], pos[3 * b + 0]);
        Y[pr] = pk2(pos[3 * a + 1], pos[3 * b + 1]);
        Z[pr] = pk2(pos[3 * a + 2], pos[3 * b + 2]);
    }
#pragma unroll
    for (int j = 0; j < PPT; ++j) md[j] = finf();

    if (tid == 0) {
        s_center = make_float4(pos[0], pos[1], pos[2], 0.0f);
        if (rank == 0) g_idx[0] = 0;
    }
    __syncthreads();

    const unsigned cross_base =
        (unsigned)__cvta_generic_to_shared(&s_cross[0][0]);

    for (int it = 1; it < MCL; ++it) {
        float4 c = s_center;
        unsigned long long ncx = pk2(-c.x, -c.x);
        unsigned long long ncy = pk2(-c.y, -c.y);
        unsigned long long ncz = pk2(-c.z, -c.z);

        float bv = fninf();
        int bi = p0;
#pragma unroll
        for (int pr = 0; pr < PPT / 2; ++pr) {
            unsigned long long ax = add2(X[pr], ncx);   // p + (-c) == p - c (IEEE-exact)
            unsigned long long ay = add2(Y[pr], ncy);
            unsigned long long az = add2(Z[pr], ncz);
            unsigned long long sx = mul2(ax, ax);
            unsigned long long sy = mul2(ay, ay);
            unsigned long long sz = mul2(az, az);
            unsigned long long s = add2(add2(sx, sy), sz);  // (dx2+dy2)+dz2
            float d0, d1;
            upk2(s, d0, d1);
            float m0 = fminf(md[2 * pr + 0], d0);
            md[2 * pr + 0] = m0;
            if (m0 > bv) { bv = m0; bi = p0 + 2 * pr + 0; }   // strict >: first idx wins
            float m1 = fminf(md[2 * pr + 1], d1);
            md[2 * pr + 1] = m1;
            if (m1 > bv) { bv = m1; bi = p0 + 2 * pr + 1; }
        }

        unsigned long long key =
            ((unsigned long long)__float_as_uint(bv) << 32) |
            (unsigned)(0xFFFFFFFFu - (unsigned)bi);
#pragma unroll
        for (int o = 16; o > 0; o >>= 1) {
            unsigned long long k2 = __shfl_down_sync(0xFFFFFFFFu, key, o);
            if (k2 > key) key = k2;
        }
        if ((tid & 31) == 0) s_wslots[tid >> 5] = key;
        __syncthreads();

        if (tid < 32) {
            unsigned long long k = (tid < FPS_THREADS / 32) ? s_wslots[tid] : 0ULL;
#pragma unroll
            for (int o = 8; o > 0; o >>= 1) {
                unsigned long long k2 = __shfl_down_sync(0xFFFFFFFFu, k, o);
                if (k2 > k) k = k2;
            }
            if (tid == 0) {
                unsigned par = (unsigned)(it & 1);
                unsigned laddr = cross_base + (par * FPS_CTAS + rank) * 8u;
#pragma unroll
                for (unsigned r = 0; r < FPS_CTAS; ++r) st_cluster_u64(laddr, r, k);
            }
        }

        asm volatile("barrier.cluster.arrive.aligned;" ::: "memory");
        asm volatile("barrier.cluster.wait.aligned;" ::: "memory");

        if (tid == 0) {
            unsigned par = (unsigned)(it & 1);
            volatile unsigned long long* vc = &s_cross[par][0];
            unsigned long long g = vc[0];
#pragma unroll
            for (int r = 1; r < FPS_CTAS; ++r) {
                unsigned long long k2 = vc[r];
                if (k2 > g) g = k2;
            }
            int idx = (int)(0xFFFFFFFFu - (unsigned)g);
            s_center = make_float4(pos[3 * idx + 0], pos[3 * idx + 1],
                                   pos[3 * idx + 2], 0.0f);
            if (rank == 0) g_idx[it] = idx;
        }
        __syncthreads();
    }
}

// ============================================================================
// 2) meta: sub_pos / sub_batch outputs
// ============================================================================
__global__ void meta_kernel(const float* __restrict__ pos,
                            const int* __restrict__ batch,
                            float* outPos, int* outBatch,
                            int writePos, int writeBatch) {
    int m = blockIdx.x * blockDim.x + threadIdx.x;
    if (m >= MCL) return;
    int idx = g_idx[m];
    if (writePos) {
        outPos[3 * m + 0] = pos[3 * idx + 0];
        outPos[3 * m + 1] = pos[3 * idx + 1];
        outPos[3 * m + 2] = pos[3 * idx + 2];
    }
    if (writeBatch) outBatch[m] = batch[idx];
}

// ============================================================================
// 3) kNN: 4 lanes/query, smem-tiled pos4, register top-16, shuffle pop-merge.
//    d = (|q|^2 - 2*dot) + |p|^2, exact f32 (matches reference expansion).
//    Merge key: total-order float encoding (self-dist may be ~-1e-7),
//    ties break on global index (matches top_k).
// ============================================================================
#define KNN_TILE 2048
__global__ void __launch_bounds__(256) knn_kernel() {
    __shared__ float4 s_p[KNN_TILE];
    const int tid = threadIdx.x;
    const int q = blockIdx.x * 64 + (tid >> 2);
    const int s = tid & 3;

    const int ci = g_idx[q];
    const float4 qp = g_pos4[ci];

    float dist[KNN_K];
    int idn[KNN_K];
#pragma unroll
    for (int u = 0; u < KNN_K; ++u) { dist[u] = finf(); idn[u] = 0; }

    for (int t0 = 0; t0 < NPTS; t0 += KNN_TILE) {
        __syncthreads();
        for (int i = tid; i < KNN_TILE; i += 256) s_p[i] = g_pos4[t0 + i];
        __syncthreads();
        for (int t = s; t < KNN_TILE; t += 4) {
            float4 p = s_p[t];
            float dot = __fadd_rn(__fadd_rn(__fmul_rn(qp.x, p.x),
                                            __fmul_rn(qp.y, p.y)),
                                  __fmul_rn(qp.z, p.z));
            float d = __fadd_rn(__fsub_rn(qp.w, __fmul_rn(2.0f, dot)), p.w);
            if (d < dist[KNN_K - 1]) {
                dist[KNN_K - 1] = d;
                idn[KNN_K - 1] = t0 + t;
#pragma unroll
                for (int u = KNN_K - 1; u > 0; --u) {
                    if (dist[u] < dist[u - 1]) {
                        float td = dist[u]; dist[u] = dist[u - 1]; dist[u - 1] = td;
                        int ti = idn[u]; idn[u] = idn[u - 1]; idn[u - 1] = ti;
                    }
                }
            }
        }
    }

#pragma unroll 1
    for (int r = 0; r < KNN_K; ++r) {
        unsigned db = __float_as_uint(dist[0]);
        db = (db & 0x80000000u) ? ~db : (db | 0x80000000u);  // total order
        unsigned long long key =
            ((unsigned long long)db << 32) |
            (unsigned)((idn[0] << 2) | s);
#pragma unroll
        for (int o = 1; o < 4; o <<= 1) {
            unsigned long long k2 = __shfl_xor_sync(0xFFFFFFFFu, key, o, 4);
            if (k2 < key) key = k2;
        }
        int wl = (int)(key & 3u);
        int hid = (int)((key >> 2) & 0x7FFFu);
        if (s == 0) g_nbr[q * KNN_K + r] = hid;
        if (s == wl) {  // pop my head
#pragma unroll
            for (int u = 0; u < KNN_K - 1; ++u) {
                dist[u] = dist[u + 1];
                idn[u] = idn[u + 1];
            }
            dist[KNN_K - 1] = finf();
        }
    }
}

// ============================================================================
// 4) GEMM: h = x @ W + b, exact f32 FFMA, 64x64 tiles
// ============================================================================
__global__ void __launch_bounds__(256) gemm_kernel(const float* __restrict__ Xm,
                                                   const float* __restrict__ Wm,
                                                   const float* __restrict__ Bv) {
    __shared__ __align__(16) float As[32][72];  // A transposed [k][row], padded
    __shared__ __align__(16) float Bs[32][64];  // [k][col]

    const int tid = threadIdx.x;
    const int tx = tid & 15, ty = tid >> 4;
    const int r0 = blockIdx.x * 64;
    const int c0 = blockIdx.y * 64;

    float acc[4][4];
#pragma unroll
    for (int i = 0; i < 4; ++i)
#pragma unroll
        for (int j = 0; j < 4; ++j) acc[i][j] = 0.0f;

    for (int kc = 0; kc < CIN; kc += 32) {
        __syncthreads();
#pragma unroll
        for (int l = 0; l < 2; ++l) {  // A: 64 rows x 32 k = 512 float4
            int fi = tid * 2 + l;
            int row = fi >> 3;
            int kf = fi & 7;
            float4 a = *(const float4*)&Xm[(r0 + row) * CIN + kc + kf * 4];
            As[kf * 4 + 0][row] = a.x;
            As[kf * 4 + 1][row] = a.y;
            As[kf * 4 + 2][row] = a.z;
            As[kf * 4 + 3][row] = a.w;
        }
#pragma unroll
        for (int l = 0; l < 2; ++l) {  // B: 32 k x 64 cols = 512 float4
            int fi = tid * 2 + l;
            int kk = fi >> 4;
            int cf = fi & 15;
            *(float4*)&Bs[kk][cf * 4] =
                *(const float4*)&Wm[(kc + kk) * COUT + c0 + cf * 4];
        }
        __syncthreads();
#pragma unroll
        for (int kk = 0; kk < 32; ++kk) {
            float4 a = *(float4*)&As[kk][ty * 4];
            float4 b = *(float4*)&Bs[kk][tx * 4];
            float av[4] = {a.x, a.y, a.z, a.w};
            float bv[4] = {b.x, b.y, b.z, b.w};
#pragma unroll
            for (int i = 0; i < 4; ++i)
#pragma unroll
                for (int j = 0; j < 4; ++j) acc[i][j] = fmaf(av[i], bv[j], acc[i][j]);
        }
    }

    float4 bias = *(const float4*)&Bv[c0 + tx * 4];
#pragma unroll
    for (int i = 0; i < 4; ++i) {
        float4 o;
        o.x = acc[i][0] + bias.x;
        o.y = acc[i][1] + bias.y;
        o.z = acc[i][2] + bias.z;
        o.w = acc[i][3] + bias.w;
        *(float4*)&g_h[(r0 + ty * 4 + i) * COUT + c0 + tx * 4] = o;
    }
}

// ============================================================================
// 5) BatchNorm stats: deterministic two-stage tree (no float atomics)
// ============================================================================
__global__ void bn_part_kernel() {
    const int c = threadIdx.x;
    const int b = blockIdx.x;
    const float* hp = g_h + (size_t)b * 128 * COUT;
    float s = 0.0f, ss = 0.0f;
#pragma unroll 4
    for (int r = 0; r < 128; ++r) {
        float v = hp[r * COUT + c];
        s += v;
        ss = fmaf(v, v, ss);
    }
    g_psum[b * COUT + c] = s;
    g_psumsq[b * COUT + c] = ss;
}

__global__ void bn_final_kernel(const float* __restrict__ gamma,
                                const float* __restrict__ beta) {
    const int c = threadIdx.x;
    float s = 0.0f, ss = 0.0f;
    for (int b = 0; b < 256; ++b) {
        s += g_psum[b * COUT + c];
        ss += g_psumsq[b * COUT + c];
    }
    const float invN = 1.0f / (float)NPTS;
    float mu = s * invN;
    float var = ss * invN - mu * mu;
    var = fmaxf(var, 0.0f);
    float sc = gamma[c] * (1.0f / sqrtf(var + 1e-5f));
    g_scale[c] = sc;
    g_shift[c] = beta[c] - mu * sc;
}

// ============================================================================
// 6) gather-max with fused BN+ReLU per gathered element
// ============================================================================
__global__ void __launch_bounds__(256) gather_kernel(float* __restrict__ out) {
    const int m = blockIdx.x;
    const int c = threadIdx.x;
    const float sc = g_scale[c];
    const float sh = g_shift[c];
    float acc = fninf();
#pragma unroll
    for (int k = 0; k < KNN_K; ++k) {
        int id = g_nbr[m * KNN_K + k];
        float v = g_h[(size_t)id * COUT + c];
        float bn = fmaxf(fmaf(v, sc, sh), 0.0f);  // ReLU(BN(v))
        acc = fmaxf(acc, bn);
    }
    out[m * COUT + c] = acc;
}

// ============================================================================
// launch
// ============================================================================
extern "C" void kernel_launch(void* const* d_in, const int* in_sizes, int n_in,
                              void* d_out, int out_size) {
    const float* x     = (const float*)d_in[0];  // [32768,128]
    const float* pos   = (const float*)d_in[1];  // [32768,3]
    const int*   batch = (const int*)d_in[2];    // [32768]
    const float* W     = (const float*)d_in[3];  // [128,256]
    const float* b     = (const float*)d_in[4];  // [256]
    const float* gamma = (const float*)d_in[5];  // [256]
    const float* beta  = (const float*)d_in[6];  // [256]
    float* out = (float*)d_out;

    const int baseOut = MCL * COUT;              // 2097152
    const int writePos = (out_size >= baseOut + MCL * 3) ? 1 : 0;
    const int writeBatch = (out_size >= baseOut + MCL * 3 + MCL) ? 1 : 0;

    prep_kernel<<<NPTS / 256, 256>>>(pos);
    fps_kernel<<<FPS_CTAS, FPS_THREADS>>>(pos);
    meta_kernel<<<MCL / 256, 256>>>(pos, batch,
                                    out + baseOut,
                                    (int*)(out + baseOut + MCL * 3),
                                    writePos, writeBatch);
    knn_kernel<<<MCL / 64, 256>>>();
    gemm_kernel<<<dim3(NPTS / 64, COUT / 64), 256>>>(x, W, b);
    bn_part_kernel<<<256, 256>>>();
    bn_final_kernel<<<1, 256>>>(gamma, beta);
    gather_kernel<<<MCL, 256>>>(out);
}